// round 5
// baseline (speedup 1.0000x reference)
#include <cuda_runtime.h>

// LocalNorm2d: 32x32 box-filter local normalization, reflect padding.
// x: (32,3,512,512) fp32 -> out same shape.
//
// Warp-independent fused version (no barriers, no smem), software-pipelined:
//   - each warp owns 128 padded cols (4/thread) x 64 output rows
//   - vertical 32-window: running register column sums; old row re-read (L2)
//   - horizontal 32-window: in-warp shfl segment sums
//   - the 3 row loads for iteration i+1 are ISSUED before the compute of
//     iteration i, hiding the ~250-cycle L2 hit latency that was previously
//     exposed on the loop-carried slide->scan dependency chain.

namespace {
constexpr int Hh   = 512;
constexpr int Ww   = 512;
constexpr int KSZ  = 32;
constexpr int PD   = 16;
constexpr int RSEG = 64;          // output rows per warp
constexpr int NSEG = Hh / RSEG;   // 8
constexpr int WOUT = 96;          // output cols per warp
constexpr int NCG  = 6;           // col groups per row band
constexpr int NWPB = 4;           // warps per block
constexpr int NT   = NWPB * 32;   // 128
constexpr int NIMG = 32 * 3;
}

__device__ __forceinline__ int rmap(int q) {   // reflect into [0, 511]
    q = q < 0 ? -q : q;
    return q > (Ww - 1) ? 2 * (Ww - 1) - q : q;
}

// v = (x - mean)/std on raw sums: (1024*x - S) * rsqrt(|1024*Q - S^2|)
__device__ __forceinline__ float norm1(float ws, float wq, float xc) {
    float V  = fabsf(fmaf(-ws, ws, 1024.0f * wq));
    float rs = __frsqrt_rn(fmaxf(V, 1e-12f));
    float v  = fmaf(1024.0f, xc, -ws) * rs;
    return fminf(6.0f, fmaxf(-6.0f, v));
}

__global__ __launch_bounds__(NT, 6)
void localnorm_kernel(const float* __restrict__ x, float* __restrict__ out)
{
    const int lane = threadIdx.x & 31;
    const int wrp  = threadIdx.x >> 5;
    const int g    = blockIdx.x * NWPB + wrp;    // 0..47
    const int seg  = g / NCG;                    // 0..7
    const int cg   = g - seg * NCG;              // 0..5
    const int img  = blockIdx.y;

    const float* __restrict__ xin = x   + (size_t)img * (Hh * Ww);
    float*       __restrict__ op  = out + (size_t)img * (Hh * Ww);

    const int  c0       = cg * WOUT + 4 * lane;      // padded col base
    const bool interior = (c0 >= PD && c0 <= Ww + PD - 4);
    const int  off      = interior ? (c0 - PD) : 0;
    int cm0 = 0, cm1 = 0, cm2 = 0, cm3 = 0;
    if (!interior) {
        cm0 = rmap(c0 + 0 - PD); cm1 = rmap(c0 + 1 - PD);
        cm2 = rmap(c0 + 2 - PD); cm3 = rmap(c0 + 3 - PD);
    }
    const int  rstart = seg * RSEG;
    const int  rend   = rstart + RSEG;
    const bool emit   = (lane < 24) && (c0 < Ww);

    float s0 = 0.f, s1 = 0.f, s2 = 0.f, s3 = 0.f;
    float q0 = 0.f, q1 = 0.f, q2 = 0.f, q3 = 0.f;

    // ---- prologue: accumulate padded rows [rstart, rstart+32) ----
    #pragma unroll 1
    for (int p = rstart; p < rstart + KSZ; ++p) {
        const float* r = xin + rmap(p - PD) * Ww;
        float4 v = interior ? *reinterpret_cast<const float4*>(r + off)
                            : make_float4(r[cm0], r[cm1], r[cm2], r[cm3]);
        s0 += v.x; s1 += v.y; s2 += v.z; s3 += v.w;
        q0 = fmaf(v.x, v.x, q0); q1 = fmaf(v.y, v.y, q1);
        q2 = fmaf(v.z, v.z, q2); q3 = fmaf(v.w, v.w, q3);
    }

    // ---- streaming pointers: at iteration index j they reference
    //      pn: row rmap(j+16), po: row rmap(j-16), pc: row j ----
    const float* pn = xin + (size_t)(rstart + PD) * Ww + off;
    const float* po = xin + (size_t)rmap(rstart - PD) * Ww + off;
    const float* pc = xin + (size_t)rstart * Ww + c0;
    float*       pw = op  + (size_t)rstart * Ww + c0;
    int dn = Ww;
    int dd = (rstart == 0) ? -Ww : Ww;
    const int flip_o = (rstart == 0) ? PD : 0x7fffffff;          // 16
    const int flip_n = (rend == Hh) ? (Hh - PD - 1) : 0x7fffffff; // 495

    auto ldrow = [&](const float* p) -> float4 {
        return interior ? *reinterpret_cast<const float4*>(p)
                        : make_float4(p[cm0], p[cm1], p[cm2], p[cm3]);
    };

    // prime the pipeline: data for iteration i = rstart
    float4 xnA = ldrow(pn);
    float4 xoA = ldrow(po);
    float4 xcA = make_float4(0.f, 0.f, 0.f, 0.f);
    if (emit) xcA = *reinterpret_cast<const float4*>(pc);
    {   // advance pointers to j = rstart + 1
        const int j = rstart;
        if (j == flip_n) dn = -Ww;
        if (j == flip_o) dd =  Ww;
        pn += dn; po += dd; pc += Ww;
    }

    #pragma unroll 1
    for (int i = rstart; i < rend; ++i) {
        // ---- prefetch iteration i+1 (LDGs issue before row-i compute) ----
        float4 xnB = ldrow(pn);
        float4 xoB = ldrow(po);
        float4 xcB;
        if (emit) xcB = *reinterpret_cast<const float4*>(pc);
        {   // advance pointers to j = i + 2 (pc clamped to last valid row)
            const int j = i + 1;
            if (j == flip_n) dn = -Ww;
            if (j == flip_o) dd =  Ww;
            pn += dn; po += dd;
            pc += (i + 2 < rend) ? Ww : 0;
        }

        // ---- compute & emit row i from current sums ----
        float i1 = s0 + s1, i2 = i1 + s2, i3 = i2 + s3;
        float j1 = q0 + q1, j2 = j1 + q2, j3 = j2 + q3;

        float as = i3 + __shfl_down_sync(0xFFFFFFFFu, i3, 1);
        float aq = j3 + __shfl_down_sync(0xFFFFFFFFu, j3, 1);
        as += __shfl_down_sync(0xFFFFFFFFu, as, 2);
        aq += __shfl_down_sync(0xFFFFFFFFu, aq, 2);
        float T8s = as + __shfl_down_sync(0xFFFFFFFFu, as, 4);
        float T8q = aq + __shfl_down_sync(0xFFFFFFFFu, aq, 4);

        float b1s = __shfl_down_sync(0xFFFFFFFFu, s0, 8);
        float b2s = __shfl_down_sync(0xFFFFFFFFu, i1, 8);
        float b3s = __shfl_down_sync(0xFFFFFFFFu, i2, 8);
        float b1q = __shfl_down_sync(0xFFFFFFFFu, q0, 8);
        float b2q = __shfl_down_sync(0xFFFFFFFFu, j1, 8);
        float b3q = __shfl_down_sync(0xFFFFFFFFu, j2, 8);

        if (emit) {
            float4 r;
            r.x = norm1(T8s,            T8q,            xcA.x);
            r.y = norm1(T8s - s0 + b1s, T8q - q0 + b1q, xcA.y);
            r.z = norm1(T8s - i1 + b2s, T8q - j1 + b2q, xcA.z);
            r.w = norm1(T8s - i2 + b3s, T8q - j2 + b3q, xcA.w);
            *reinterpret_cast<float4*>(pw) = r;
        }
        pw += Ww;

        // ---- slide vertical window with the CURRENT stage's rows ----
        s0 += xnA.x - xoA.x; s1 += xnA.y - xoA.y;
        s2 += xnA.z - xoA.z; s3 += xnA.w - xoA.w;
        q0 = fmaf(xnA.x, xnA.x, q0); q0 = fmaf(-xoA.x, xoA.x, q0);
        q1 = fmaf(xnA.y, xnA.y, q1); q1 = fmaf(-xoA.y, xoA.y, q1);
        q2 = fmaf(xnA.z, xnA.z, q2); q2 = fmaf(-xoA.z, xoA.z, q2);
        q3 = fmaf(xnA.w, xnA.w, q3); q3 = fmaf(-xoA.w, xoA.w, q3);

        // rotate pipeline stage
        xnA = xnB; xoA = xoB; xcA = xcB;
    }
}

extern "C" void kernel_launch(void* const* d_in, const int* in_sizes, int n_in,
                              void* d_out, int out_size) {
    const float* x = (const float*)d_in[0];
    float* out = (float*)d_out;
    (void)in_sizes; (void)n_in; (void)out_size;

    dim3 grid(NSEG * NCG / NWPB, NIMG);   // (12, 96) = 1152 blocks
    localnorm_kernel<<<grid, NT>>>(x, out);
}

// round 6
// speedup vs baseline: 1.4005x; 1.4005x over previous
#include <cuda_runtime.h>

// LocalNorm2d: 32x32 box-filter local normalization, reflect padding.
// x: (32,3,512,512) fp32 -> out same shape.
//
// Warp-independent fused kernel (no barriers, no smem):
//   - each warp: 128 padded cols (4/thread) x 64 output rows
//   - vertical 32-window: running register column sums (old row re-read, L2 hit)
//   - horizontal 32-window: in-warp shfl segment sums
//   - KEY (this round): the column-reflection fallback path is compiled ONLY
//     into the two edge column-groups via run_warp<EDGE>; the 4 interior
//     groups get a branch-free, vector-load-only body. Previously the scalar
//     gather fallback was predicated into EVERY warp's instruction stream,
//     doubling issued instructions.

namespace {
constexpr int Hh   = 512;
constexpr int Ww   = 512;
constexpr int KSZ  = 32;
constexpr int PD   = 16;
constexpr int RSEG = 64;          // output rows per warp
constexpr int NSEG = Hh / RSEG;   // 8
constexpr int WOUT = 96;          // output cols per warp
constexpr int NCG  = 6;           // col groups per row band
constexpr int NWPB = 8;           // warps per block
constexpr int NT   = NWPB * 32;   // 256
constexpr int NIMG = 32 * 3;
}

__device__ __forceinline__ int rmap(int q) {   // reflect into [0, 511]
    q = q < 0 ? -q : q;
    return q > (Ww - 1) ? 2 * (Ww - 1) - q : q;
}

// v = (x - mean)/std on raw sums: (1024*x - S) * rsqrt(|1024*Q - S^2|)
__device__ __forceinline__ float norm1(float ws, float wq, float xc) {
    float V  = fabsf(fmaf(-ws, ws, 1024.0f * wq));
    float rs = __frsqrt_rn(fmaxf(V, 1e-12f));
    float v  = fmaf(1024.0f, xc, -ws) * rs;
    return fminf(6.0f, fmaxf(-6.0f, v));
}

template<bool EDGE>
__device__ __forceinline__ void run_warp(
    const float* __restrict__ xin, float* __restrict__ op,
    int lane, int cg, int rstart)
{
    const int  c0       = cg * WOUT + 4 * lane;      // padded col base
    const bool interior = !EDGE || (c0 >= PD && c0 <= Ww + PD - 4);
    const int  off      = interior ? (c0 - PD) : 0;
    int cm0 = 0, cm1 = 0, cm2 = 0, cm3 = 0;
    if (EDGE && !interior) {
        cm0 = rmap(c0 + 0 - PD); cm1 = rmap(c0 + 1 - PD);
        cm2 = rmap(c0 + 2 - PD); cm3 = rmap(c0 + 3 - PD);
    }
    const int  rend = rstart + RSEG;
    const bool emit = (lane < 24) && (!EDGE || c0 < Ww);

    auto ldrow = [&](const float* p) -> float4 {
        if (!EDGE) return *reinterpret_cast<const float4*>(p);
        return interior ? *reinterpret_cast<const float4*>(p)
                        : make_float4(p[cm0], p[cm1], p[cm2], p[cm3]);
    };

    float s0 = 0.f, s1 = 0.f, s2 = 0.f, s3 = 0.f;
    float q0 = 0.f, q1 = 0.f, q2 = 0.f, q3 = 0.f;

    // ---- prologue: accumulate padded rows [rstart, rstart+32) ----
    #pragma unroll 1
    for (int p = rstart; p < rstart + KSZ; ++p) {
        const float* r = xin + rmap(p - PD) * Ww + off;
        float4 v = ldrow(r);
        s0 += v.x; s1 += v.y; s2 += v.z; s3 += v.w;
        q0 = fmaf(v.x, v.x, q0); q1 = fmaf(v.y, v.y, q1);
        q2 = fmaf(v.z, v.z, q2); q3 = fmaf(v.w, v.w, q3);
    }

    // ---- streaming row pointers; reflection = stride sign flip ----
    const float* pn = xin + (size_t)(rstart + PD) * Ww + off;          // row rmap(i+16)
    const float* po = xin + (size_t)rmap(rstart - PD) * Ww + off;      // row rmap(i-16)
    const float* pc = xin + (size_t)rstart * Ww + c0;                  // row i (center)
    float*       pw = op  + (size_t)rstart * Ww + c0;
    int dn = Ww;
    int dd = (rstart == 0) ? -Ww : Ww;
    const int flip_o = (rstart == 0) ? PD : 0x7fffffff;           // i == 16
    const int flip_n = (rend == Hh) ? (Hh - PD - 1) : 0x7fffffff; // i == 495

    #pragma unroll 2
    for (int i = rstart; i < rend; ++i) {
        float4 xn = ldrow(pn);
        float4 xo = ldrow(po);
        if (i == flip_n) dn = -Ww;
        if (i == flip_o) dd =  Ww;
        pn += dn; po += dd;
        float4 xc;
        if (emit) xc = *reinterpret_cast<const float4*>(pc);
        pc += Ww;

        // thread-local partial prefixes over own 4 cols
        float i1 = s0 + s1, i2 = i1 + s2, i3 = i2 + s3;
        float j1 = q0 + q1, j2 = j1 + q2, j3 = j2 + q3;

        // segment sum of 8 consecutive thread totals (lanes t..t+7)
        float as = i3 + __shfl_down_sync(0xFFFFFFFFu, i3, 1);
        float aq = j3 + __shfl_down_sync(0xFFFFFFFFu, j3, 1);
        as += __shfl_down_sync(0xFFFFFFFFu, as, 2);
        aq += __shfl_down_sync(0xFFFFFFFFu, aq, 2);
        float T8s = as + __shfl_down_sync(0xFFFFFFFFu, as, 4);
        float T8q = aq + __shfl_down_sync(0xFFFFFFFFu, aq, 4);

        // partial prefixes of thread t+8
        float b1s = __shfl_down_sync(0xFFFFFFFFu, s0, 8);
        float b2s = __shfl_down_sync(0xFFFFFFFFu, i1, 8);
        float b3s = __shfl_down_sync(0xFFFFFFFFu, i2, 8);
        float b1q = __shfl_down_sync(0xFFFFFFFFu, q0, 8);
        float b2q = __shfl_down_sync(0xFFFFFFFFu, j1, 8);
        float b3q = __shfl_down_sync(0xFFFFFFFFu, j2, 8);

        if (emit) {
            float4 r;
            r.x = norm1(T8s,            T8q,            xc.x);
            r.y = norm1(T8s - s0 + b1s, T8q - q0 + b1q, xc.y);
            r.z = norm1(T8s - i1 + b2s, T8q - j1 + b2q, xc.z);
            r.w = norm1(T8s - i2 + b3s, T8q - j2 + b3q, xc.w);
            *reinterpret_cast<float4*>(pw) = r;
        }
        pw += Ww;

        // slide vertical window
        s0 += xn.x - xo.x; s1 += xn.y - xo.y;
        s2 += xn.z - xo.z; s3 += xn.w - xo.w;
        q0 = fmaf(xn.x, xn.x, q0); q0 = fmaf(-xo.x, xo.x, q0);
        q1 = fmaf(xn.y, xn.y, q1); q1 = fmaf(-xo.y, xo.y, q1);
        q2 = fmaf(xn.z, xn.z, q2); q2 = fmaf(-xo.z, xo.z, q2);
        q3 = fmaf(xn.w, xn.w, q3); q3 = fmaf(-xo.w, xo.w, q3);
    }
}

__global__ __launch_bounds__(NT, 4)
void localnorm_kernel(const float* __restrict__ x, float* __restrict__ out)
{
    const int lane = threadIdx.x & 31;
    const int wrp  = threadIdx.x >> 5;
    const int g    = blockIdx.x * NWPB + wrp;    // 0..47
    const int seg  = g / NCG;                    // 0..7
    const int cg   = g - seg * NCG;              // 0..5
    const int img  = blockIdx.y;

    const float* __restrict__ xin = x   + (size_t)img * (Hh * Ww);
    float*       __restrict__ op  = out + (size_t)img * (Hh * Ww);

    // warp-uniform branch: only edge column-groups compile the gather path
    if (cg == 0 || cg == NCG - 1) {
        run_warp<true >(xin, op, lane, cg, seg * RSEG);
    } else {
        run_warp<false>(xin, op, lane, cg, seg * RSEG);
    }
}

extern "C" void kernel_launch(void* const* d_in, const int* in_sizes, int n_in,
                              void* d_out, int out_size) {
    const float* x = (const float*)d_in[0];
    float* out = (float*)d_out;
    (void)in_sizes; (void)n_in; (void)out_size;

    dim3 grid(NSEG * NCG / NWPB, NIMG);   // (6, 96) = 576 blocks
    localnorm_kernel<<<grid, NT>>>(x, out);
}